// round 11
// baseline (speedup 1.0000x reference)
#include <cuda_runtime.h>
#include <cstdint>

// Problem constants
#define NB 2048   // batch
#define NT 1024   // timesteps
#define ND 64     // input size
#define NH 32     // hidden
#define NG 96     // 3*H

// ---------------- packed f32x2 helpers ----------------
typedef unsigned long long u64t;

__device__ __forceinline__ u64t ffma2(u64t a, u64t b, u64t c) {
    u64t d;
    asm("fma.rn.f32x2 %0, %1, %2, %3;" : "=l"(d) : "l"(a), "l"(b), "l"(c));
    return d;
}
__device__ __forceinline__ u64t add2(u64t a, u64t b) {
    u64t d;
    asm("add.rn.f32x2 %0, %1, %2;" : "=l"(d) : "l"(a), "l"(b));
    return d;
}
__device__ __forceinline__ u64t pack2(float lo, float hi) {
    u64t d;
    asm("mov.b64 %0, {%1, %2};" : "=l"(d) : "r"(__float_as_uint(lo)), "r"(__float_as_uint(hi)));
    return d;
}
__device__ __forceinline__ u64t dup2(float v) { return pack2(v, v); }
__device__ __forceinline__ float2 unpack2(u64t p) {
    unsigned lo, hi;
    asm("mov.b64 {%0, %1}, %2;" : "=r"(lo), "=r"(hi) : "l"(p));
    return make_float2(__uint_as_float(lo), __uint_as_float(hi));
}

__device__ __forceinline__ float sigm(float x) {
    return __fdividef(1.0f, 1.0f + __expf(-x));
}
__device__ __forceinline__ float tanh_fast(float x) {
    return 1.0f - __fdividef(2.0f, __expf(2.0f * x) + 1.0f);
}

// Scratch: gx pre-activations, batch-pair interleaved f32x2.
__device__ u64t g_gx[(size_t)(NB / 2) * NT * NG];

// ============================================================
// Phase 1 (persistent): gx = w_ih0 @ x  for all (b,t)
// ============================================================
#define P1_THREADS 256
#define P1_BLOCKS 148
#define P1_WARPS (P1_BLOCKS * 8)
#define P1_NTILES ((NB / 2) * (NT / 4))

__global__ void __launch_bounds__(P1_THREADS, 1) gx_gemm_kernel(
    const float* __restrict__ x,
    const float* __restrict__ w_ih0)
{
    __shared__ __align__(16) float ws[NG * ND];
    __shared__ __align__(16) float xs_all[8 * 512];

    const int tid = threadIdx.x;
    for (int i = tid; i < NG * ND; i += P1_THREADS) {
        int uu = i >> 6, k = i & 63;
        int k4 = k >> 2, kk = k & 3;
        ws[uu * 64 + (((k4 ^ (uu & 7)) << 2) | kk)] = w_ih0[i];
    }
    __syncthreads();

    const int wid = tid >> 5, lane = tid & 31;
    const int u = lane, s = lane & 7;
    float* xs = xs_all + wid * 512;
    const float4* ws4 = (const float4*)ws;

    const int gwarp = blockIdx.x * 8 + wid;

    float4 v[4];
    {
        int pb = gwarp >> 8, tt = (gwarp & 255) << 2;
        const float4* bb0 = (const float4*)(x + ((size_t)(2 * pb) * NT + tt) * ND);
        const float4* bb1 = (const float4*)(x + ((size_t)(2 * pb + 1) * NT + tt) * ND);
        #pragma unroll
        for (int i = 0; i < 4; ++i) {
            int j = lane + 32 * i;
            v[i] = (j >= 64) ? bb1[j & 63] : bb0[j];
        }
    }

    for (int T = gwarp; T < P1_NTILES; T += P1_WARPS) {
        const int pb = T >> 8, tt = (T & 255) << 2;

        __syncwarp();
        #pragma unroll
        for (int i = 0; i < 4; ++i) {
            int j = lane + 32 * i;
            int e = j >> 6, jj = j & 63;
            int t_loc = jj >> 4, k4 = jj & 15;
            float* dst = xs + t_loc * 128 + 8 * k4 + e;
            dst[0] = v[i].x; dst[2] = v[i].y; dst[4] = v[i].z; dst[6] = v[i].w;
        }
        __syncwarp();

        const int Tn = T + P1_WARPS;
        if (Tn < P1_NTILES) {
            int pbn = Tn >> 8, ttn = (Tn & 255) << 2;
            const float4* bb0 = (const float4*)(x + ((size_t)(2 * pbn) * NT + ttn) * ND);
            const float4* bb1 = (const float4*)(x + ((size_t)(2 * pbn + 1) * NT + ttn) * ND);
            #pragma unroll
            for (int i = 0; i < 4; ++i) {
                int j = lane + 32 * i;
                v[i] = (j >= 64) ? bb1[j & 63] : bb0[j];
            }
        }

        u64t accr[4], accz[4], accn[4];
        #pragma unroll
        for (int p = 0; p < 4; ++p) { accr[p] = 0ull; accz[p] = 0ull; accn[p] = 0ull; }

        #pragma unroll
        for (int k4 = 0; k4 < 16; ++k4) {
            const int pp = k4 ^ s;
            float4 wr = ws4[u * 16 + pp];
            float4 wz = ws4[(32 + u) * 16 + pp];
            float4 wn = ws4[(64 + u) * 16 + pp];
            u64t dr0 = dup2(wr.x), dr1 = dup2(wr.y), dr2 = dup2(wr.z), dr3 = dup2(wr.w);
            u64t dz0 = dup2(wz.x), dz1 = dup2(wz.y), dz2 = dup2(wz.z), dz3 = dup2(wz.w);
            u64t dn0 = dup2(wn.x), dn1 = dup2(wn.y), dn2 = dup2(wn.z), dn3 = dup2(wn.w);
            #pragma unroll
            for (int p = 0; p < 4; ++p) {
                const ulonglong2* vp = (const ulonglong2*)(xs + p * 128 + 8 * k4);
                ulonglong2 v01 = vp[0];
                ulonglong2 v23 = vp[1];
                accr[p] = ffma2(dr0, v01.x, accr[p]); accr[p] = ffma2(dr1, v01.y, accr[p]);
                accr[p] = ffma2(dr2, v23.x, accr[p]); accr[p] = ffma2(dr3, v23.y, accr[p]);
                accz[p] = ffma2(dz0, v01.x, accz[p]); accz[p] = ffma2(dz1, v01.y, accz[p]);
                accz[p] = ffma2(dz2, v23.x, accz[p]); accz[p] = ffma2(dz3, v23.y, accz[p]);
                accn[p] = ffma2(dn0, v01.x, accn[p]); accn[p] = ffma2(dn1, v01.y, accn[p]);
                accn[p] = ffma2(dn2, v23.x, accn[p]); accn[p] = ffma2(dn3, v23.y, accn[p]);
            }
        }

        #pragma unroll
        for (int p = 0; p < 4; ++p) {
            u64t* o = g_gx + ((size_t)pb * NT + tt + p) * NG;
            o[u]      = accr[p];
            o[32 + u] = accz[p];
            o[64 + u] = accn[p];
        }
    }
}

// ============================================================
// Phase 2: recurrence, layer-skewed software pipeline.
// At loop iter t: compute L0(t) and L1(t-1) fused (independent).
// 128 blocks x 4 warps, 4 rows/warp (pair-buffers A,B).
// ============================================================
#define WPB2 4
#define NBLK2 128
#define NTHR2 (WPB2 * 32)

// L0 GEMM block over shared h0 pairs (a01..b23 already loaded)
#define L0_FFMA(WR, WZ, WN)                                                    \
    {                                                                          \
        u64t r0 = dup2((WR).x), r1 = dup2((WR).y), r2 = dup2((WR).z), r3 = dup2((WR).w); \
        u64t z0 = dup2((WZ).x), z1 = dup2((WZ).y), z2 = dup2((WZ).z), z3 = dup2((WZ).w); \
        u64t n0 = dup2((WN).x), n1 = dup2((WN).y), n2 = dup2((WN).z), n3 = dup2((WN).w); \
        arA  = ffma2(r0, a01.x, arA);  arA  = ffma2(r1, a01.y, arA);           \
        arA  = ffma2(r2, a23.x, arA);  arA  = ffma2(r3, a23.y, arA);           \
        azA  = ffma2(z0, a01.x, azA);  azA  = ffma2(z1, a01.y, azA);           \
        azA  = ffma2(z2, a23.x, azA);  azA  = ffma2(z3, a23.y, azA);           \
        anhA = ffma2(n0, a01.x, anhA); anhA = ffma2(n1, a01.y, anhA);          \
        anhA = ffma2(n2, a23.x, anhA); anhA = ffma2(n3, a23.y, anhA);          \
        arB  = ffma2(r0, b01.x, arB);  arB  = ffma2(r1, b01.y, arB);           \
        arB  = ffma2(r2, b23.x, arB);  arB  = ffma2(r3, b23.y, arB);           \
        azB  = ffma2(z0, b01.x, azB);  azB  = ffma2(z1, b01.y, azB);           \
        azB  = ffma2(z2, b23.x, azB);  azB  = ffma2(z3, b23.y, azB);           \
        anhB = ffma2(n0, b01.x, anhB); anhB = ffma2(n1, b01.y, anhB);          \
        anhB = ffma2(n2, b23.x, anhB); anhB = ffma2(n3, b23.y, anhB);          \
    }

// L1 input GEMM (over shared h0 pairs, acc cnx)
#define L1X_FFMA(WR, WZ, WN)                                                   \
    {                                                                          \
        u64t r0 = dup2((WR).x), r1 = dup2((WR).y), r2 = dup2((WR).z), r3 = dup2((WR).w); \
        u64t z0 = dup2((WZ).x), z1 = dup2((WZ).y), z2 = dup2((WZ).z), z3 = dup2((WZ).w); \
        u64t n0 = dup2((WN).x), n1 = dup2((WN).y), n2 = dup2((WN).z), n3 = dup2((WN).w); \
        crA  = ffma2(r0, a01.x, crA);  crA  = ffma2(r1, a01.y, crA);           \
        crA  = ffma2(r2, a23.x, crA);  crA  = ffma2(r3, a23.y, crA);           \
        czA  = ffma2(z0, a01.x, czA);  czA  = ffma2(z1, a01.y, czA);           \
        czA  = ffma2(z2, a23.x, czA);  czA  = ffma2(z3, a23.y, czA);           \
        cnxA = ffma2(n0, a01.x, cnxA); cnxA = ffma2(n1, a01.y, cnxA);          \
        cnxA = ffma2(n2, a23.x, cnxA); cnxA = ffma2(n3, a23.y, cnxA);          \
        crB  = ffma2(r0, b01.x, crB);  crB  = ffma2(r1, b01.y, crB);           \
        crB  = ffma2(r2, b23.x, crB);  crB  = ffma2(r3, b23.y, crB);           \
        czB  = ffma2(z0, b01.x, czB);  czB  = ffma2(z1, b01.y, czB);           \
        czB  = ffma2(z2, b23.x, czB);  czB  = ffma2(z3, b23.y, czB);           \
        cnxB = ffma2(n0, b01.x, cnxB); cnxB = ffma2(n1, b01.y, cnxB);          \
        cnxB = ffma2(n2, b23.x, cnxB); cnxB = ffma2(n3, b23.y, cnxB);          \
    }

// L1 hidden GEMM (over h1(t-2) pairs qa/qb, acc cnh)
#define L1H_FFMA(WR, WZ, WN)                                                   \
    {                                                                          \
        u64t r0 = dup2((WR).x), r1 = dup2((WR).y), r2 = dup2((WR).z), r3 = dup2((WR).w); \
        u64t z0 = dup2((WZ).x), z1 = dup2((WZ).y), z2 = dup2((WZ).z), z3 = dup2((WZ).w); \
        u64t n0 = dup2((WN).x), n1 = dup2((WN).y), n2 = dup2((WN).z), n3 = dup2((WN).w); \
        crA  = ffma2(r0, qa01.x, crA);  crA  = ffma2(r1, qa01.y, crA);         \
        crA  = ffma2(r2, qa23.x, crA);  crA  = ffma2(r3, qa23.y, crA);         \
        czA  = ffma2(z0, qa01.x, czA);  czA  = ffma2(z1, qa01.y, czA);         \
        czA  = ffma2(z2, qa23.x, czA);  czA  = ffma2(z3, qa23.y, czA);         \
        cnhA = ffma2(n0, qa01.x, cnhA); cnhA = ffma2(n1, qa01.y, cnhA);        \
        cnhA = ffma2(n2, qa23.x, cnhA); cnhA = ffma2(n3, qa23.y, cnhA);        \
        crB  = ffma2(r0, qb01.x, crB);  crB  = ffma2(r1, qb01.y, crB);         \
        crB  = ffma2(r2, qb23.x, crB);  crB  = ffma2(r3, qb23.y, crB);         \
        czB  = ffma2(z0, qb01.x, czB);  czB  = ffma2(z1, qb01.y, czB);         \
        czB  = ffma2(z2, qb23.x, czB);  czB  = ffma2(z3, qb23.y, czB);         \
        cnhB = ffma2(n0, qb01.x, cnhB); cnhB = ffma2(n1, qb01.y, cnhB);        \
        cnhB = ffma2(n2, qb23.x, cnhB); cnhB = ffma2(n3, qb23.y, cnhB);        \
    }

__global__ void __launch_bounds__(NTHR2, 1) gru_recurrent_kernel(
    const float* __restrict__ w_hh0,
    const float* __restrict__ b_ih0, const float* __restrict__ b_hh0,
    const float* __restrict__ w_ih1, const float* __restrict__ w_hh1,
    const float* __restrict__ b_ih1, const float* __restrict__ b_hh1,
    const float* __restrict__ w_cls, const float* __restrict__ b_cls,
    float* __restrict__ out)
{
    __shared__ __align__(16) float whh0s[NG * NH];
    __shared__ __align__(16) float wh1s[NG * NH];
    __shared__ __align__(16) u64t sh0u_all[WPB2 * 64];
    __shared__ __align__(16) u64t sh1u_all[WPB2 * 64];

    const int tid = threadIdx.x;
    for (int i = tid; i < NG * NH; i += NTHR2) {
        int g = i >> 5, k = i & 31;
        int k4 = k >> 2, kk = k & 3;
        int ph = g * 32 + (((k4 ^ (g & 7)) << 2) | kk);
        whh0s[ph] = w_hh0[i];
        wh1s[ph]  = w_hh1[i];
    }
    for (int i = tid; i < WPB2 * 64; i += NTHR2) {
        sh0u_all[i] = 0ull;
        sh1u_all[i] = 0ull;
    }
    __syncthreads();

    const int wid = tid >> 5, lane = tid & 31;
    const int q = blockIdx.x * WPB2 + wid;
    const int b0 = q * 4;
    const int u = lane, s = lane & 7;

    u64t* sh0u = sh0u_all + wid * 64;
    u64t* sh1u = sh1u_all + wid * 64;

    // register-cache w_ih1 rows u, 32+u, 64+u
    float4 wi1r[8], wi1z[8], wi1n[8];
    {
        const float4* a = (const float4*)(w_ih1 + u * NH);
        const float4* b = (const float4*)(w_ih1 + (32 + u) * NH);
        const float4* c = (const float4*)(w_ih1 + (64 + u) * NH);
        #pragma unroll
        for (int i = 0; i < 8; ++i) { wi1r[i] = a[i]; wi1z[i] = b[i]; wi1n[i] = c[i]; }
    }

    const u64t br0d  = dup2(b_ih0[u]      + b_hh0[u]);
    const u64t bz0d  = dup2(b_ih0[32 + u] + b_hh0[32 + u]);
    const u64t bnx0d = dup2(b_ih0[64 + u]);
    const u64t bnh0d = dup2(b_hh0[64 + u]);
    const u64t br1d  = dup2(b_ih1[u]      + b_hh1[u]);
    const u64t bz1d  = dup2(b_ih1[32 + u] + b_hh1[32 + u]);
    const u64t bnx1d = dup2(b_ih1[64 + u]);
    const u64t bnh1d = dup2(b_hh1[64 + u]);

    const u64t* gxA = g_gx + (size_t)(2 * q) * NT * NG;
    const u64t* gxB = gxA + (size_t)NT * NG;

    u64t pAr = gxA[u], pAz = gxA[32 + u], pAn = gxA[64 + u];
    u64t pBr = gxB[u], pBz = gxB[32 + u], pBn = gxB[64 + u];

    float hA0 = 0.0f, hA1 = 0.0f, hB0 = 0.0f, hB1 = 0.0f;   // layer0 h
    float jA0 = 0.0f, jA1 = 0.0f, jB0 = 0.0f, jB1 = 0.0f;   // layer1 h

    const float4* whh0s4 = (const float4*)whh0s;
    const float4* wh1s4  = (const float4*)wh1s;
    const ulonglong2* hpA = (const ulonglong2*)sh0u;
    const ulonglong2* hpB = (const ulonglong2*)(sh0u + 32);
    const ulonglong2* qpA = (const ulonglong2*)sh1u;
    const ulonglong2* qpB = (const ulonglong2*)(sh1u + 32);

    // ---------- peel: L0(0) only (sh0 is zero, GEMM contributes 0) ----------
    {
        float2 fr = unpack2(add2(br0d, pAr));
        float2 fz = unpack2(add2(bz0d, pAz));
        float2 fnx = unpack2(add2(bnx0d, pAn));
        float2 fnh = unpack2(bnh0d);
        float r0 = sigm(fr.x), z0 = sigm(fz.x);
        float n0 = tanh_fast(fmaf(r0, fnh.x, fnx.x));
        hA0 = n0 - z0 * n0;   // h_prev = 0
        float r1 = sigm(fr.y), z1 = sigm(fz.y);
        float n1 = tanh_fast(fmaf(r1, fnh.y, fnx.y));
        hA1 = n1 - z1 * n1;

        fr = unpack2(add2(br0d, pBr));
        fz = unpack2(add2(bz0d, pBz));
        fnx = unpack2(add2(bnx0d, pBn));
        r0 = sigm(fr.x); z0 = sigm(fz.x);
        n0 = tanh_fast(fmaf(r0, fnh.x, fnx.x));
        hB0 = n0 - z0 * n0;
        r1 = sigm(fr.y); z1 = sigm(fz.y);
        n1 = tanh_fast(fmaf(r1, fnh.y, fnx.y));
        hB1 = n1 - z1 * n1;

        // load gx(1)
        const u64t* a = gxA + NG;
        const u64t* b = gxB + NG;
        pAr = a[u]; pAz = a[32 + u]; pAn = a[64 + u];
        pBr = b[u]; pBz = b[32 + u]; pBn = b[64 + u];

        __syncwarp();
        sh0u[u]      = pack2(hA0, hA1);
        sh0u[32 + u] = pack2(hB0, hB1);
        __syncwarp();
    }

    // ---------- fused loop: t = 1..NT-1 computes L0(t) + L1(t-1) ----------
    for (int t = 1; t < NT; ++t) {
        u64t arA = add2(br0d, pAr), azA = add2(bz0d, pAz), anxA = add2(bnx0d, pAn);
        u64t arB = add2(br0d, pBr), azB = add2(bz0d, pBz), anxB = add2(bnx0d, pBn);
        u64t anhA = bnh0d, anhB = bnh0d;
        u64t crA = br1d, czA = bz1d, cnxA = bnx1d, cnhA = bnh1d;
        u64t crB = br1d, czB = bz1d, cnxB = bnx1d, cnhB = bnh1d;

        if (t + 1 < NT) {
            const u64t* a = gxA + (size_t)(t + 1) * NG;
            const u64t* b = gxB + (size_t)(t + 1) * NG;
            pAr = a[u]; pAz = a[32 + u]; pAn = a[64 + u];
            pBr = b[u]; pBz = b[32 + u]; pBn = b[64 + u];
        }

        #pragma unroll
        for (int i = 0; i < 8; ++i) {
            const int pp = i ^ s;
            // shared h0(t-1) pairs (used by both L0 and L1-input)
            ulonglong2 a01 = hpA[2 * i], a23 = hpA[2 * i + 1];
            ulonglong2 b01 = hpB[2 * i], b23 = hpB[2 * i + 1];
            // L0: whh0 (smem, swizzled)
            {
                float4 wr = whh0s4[u * 8 + pp];
                float4 wz = whh0s4[(32 + u) * 8 + pp];
                float4 wn = whh0s4[(64 + u) * 8 + pp];
                L0_FFMA(wr, wz, wn);
            }
            // L1 input: wi1 (registers)
            L1X_FFMA(wi1r[i], wi1z[i], wi1n[i]);
            // L1 hidden: wh1 (smem) x h1(t-2) pairs
            ulonglong2 qa01 = qpA[2 * i], qa23 = qpA[2 * i + 1];
            ulonglong2 qb01 = qpB[2 * i], qb23 = qpB[2 * i + 1];
            {
                float4 vr = wh1s4[u * 8 + pp];
                float4 vz = wh1s4[(32 + u) * 8 + pp];
                float4 vn = wh1s4[(64 + u) * 8 + pp];
                L1H_FFMA(vr, vz, vn);
            }
        }

        // activations: layer0 -> h(t), layer1 -> j(t-1); independent chains
        {
            float2 fr = unpack2(arA), fz = unpack2(azA);
            float2 fnx = unpack2(anxA), fnh = unpack2(anhA);
            float r0 = sigm(fr.x), z0 = sigm(fz.x);
            float n0 = tanh_fast(fmaf(r0, fnh.x, fnx.x));
            hA0 = n0 + z0 * (hA0 - n0);
            float r1 = sigm(fr.y), z1 = sigm(fz.y);
            float n1 = tanh_fast(fmaf(r1, fnh.y, fnx.y));
            hA1 = n1 + z1 * (hA1 - n1);
        }
        {
            float2 fr = unpack2(arB), fz = unpack2(azB);
            float2 fnx = unpack2(anxB), fnh = unpack2(anhB);
            float r0 = sigm(fr.x), z0 = sigm(fz.x);
            float n0 = tanh_fast(fmaf(r0, fnh.x, fnx.x));
            hB0 = n0 + z0 * (hB0 - n0);
            float r1 = sigm(fr.y), z1 = sigm(fz.y);
            float n1 = tanh_fast(fmaf(r1, fnh.y, fnx.y));
            hB1 = n1 + z1 * (hB1 - n1);
        }
        {
            float2 fr = unpack2(crA), fz = unpack2(czA);
            float2 fnx = unpack2(cnxA), fnh = unpack2(cnhA);
            float r0 = sigm(fr.x), z0 = sigm(fz.x);
            float n0 = tanh_fast(fmaf(r0, fnh.x, fnx.x));
            jA0 = n0 + z0 * (jA0 - n0);
            float r1 = sigm(fr.y), z1 = sigm(fz.y);
            float n1 = tanh_fast(fmaf(r1, fnh.y, fnx.y));
            jA1 = n1 + z1 * (jA1 - n1);
        }
        {
            float2 fr = unpack2(crB), fz = unpack2(czB);
            float2 fnx = unpack2(cnxB), fnh = unpack2(cnhB);
            float r0 = sigm(fr.x), z0 = sigm(fz.x);
            float n0 = tanh_fast(fmaf(r0, fnh.x, fnx.x));
            jB0 = n0 + z0 * (jB0 - n0);
            float r1 = sigm(fr.y), z1 = sigm(fz.y);
            float n1 = tanh_fast(fmaf(r1, fnh.y, fnx.y));
            jB1 = n1 + z1 * (jB1 - n1);
        }

        __syncwarp();
        sh0u[u]      = pack2(hA0, hA1);
        sh0u[32 + u] = pack2(hB0, hB1);
        sh1u[u]      = pack2(jA0, jA1);
        sh1u[32 + u] = pack2(jB0, jB1);
        __syncwarp();
    }

    // ---------- drain: L1(NT-1) using sh0=h0(NT-1), sh1=h1(NT-2) ----------
    {
        u64t crA = br1d, czA = bz1d, cnxA = bnx1d, cnhA = bnh1d;
        u64t crB = br1d, czB = bz1d, cnxB = bnx1d, cnhB = bnh1d;
        #pragma unroll
        for (int i = 0; i < 8; ++i) {
            const int pp = i ^ s;
            ulonglong2 a01 = hpA[2 * i], a23 = hpA[2 * i + 1];
            ulonglong2 b01 = hpB[2 * i], b23 = hpB[2 * i + 1];
            L1X_FFMA(wi1r[i], wi1z[i], wi1n[i]);
            ulonglong2 qa01 = qpA[2 * i], qa23 = qpA[2 * i + 1];
            ulonglong2 qb01 = qpB[2 * i], qb23 = qpB[2 * i + 1];
            {
                float4 vr = wh1s4[u * 8 + pp];
                float4 vz = wh1s4[(32 + u) * 8 + pp];
                float4 vn = wh1s4[(64 + u) * 8 + pp];
                L1H_FFMA(vr, vz, vn);
            }
        }
        {
            float2 fr = unpack2(crA), fz = unpack2(czA);
            float2 fnx = unpack2(cnxA), fnh = unpack2(cnhA);
            float r0 = sigm(fr.x), z0 = sigm(fz.x);
            float n0 = tanh_fast(fmaf(r0, fnh.x, fnx.x));
            jA0 = n0 + z0 * (jA0 - n0);
            float r1 = sigm(fr.y), z1 = sigm(fz.y);
            float n1 = tanh_fast(fmaf(r1, fnh.y, fnx.y));
            jA1 = n1 + z1 * (jA1 - n1);
        }
        {
            float2 fr = unpack2(crB), fz = unpack2(czB);
            float2 fnx = unpack2(cnxB), fnh = unpack2(cnhB);
            float r0 = sigm(fr.x), z0 = sigm(fz.x);
            float n0 = tanh_fast(fmaf(r0, fnh.x, fnx.x));
            jB0 = n0 + z0 * (jB0 - n0);
            float r1 = sigm(fr.y), z1 = sigm(fz.y);
            float n1 = tanh_fast(fmaf(r1, fnh.y, fnx.y));
            jB1 = n1 + z1 * (jB1 - n1);
        }
    }

    // ---- epilogue: hidden states + classifier ----
    out[NB + (b0 + 0) * NH + u] = hA0;
    out[NB + (b0 + 1) * NH + u] = hA1;
    out[NB + (b0 + 2) * NH + u] = hB0;
    out[NB + (b0 + 3) * NH + u] = hB1;
    out[NB + NB * NH + (b0 + 0) * NH + u] = jA0;
    out[NB + NB * NH + (b0 + 1) * NH + u] = jA1;
    out[NB + NB * NH + (b0 + 2) * NH + u] = jB0;
    out[NB + NB * NH + (b0 + 3) * NH + u] = jB1;

    float wc = w_cls[u];
    float p0 = jA0 * wc, p1 = jA1 * wc, p2 = jB0 * wc, p3 = jB1 * wc;
    #pragma unroll
    for (int o = 16; o > 0; o >>= 1) {
        p0 += __shfl_xor_sync(0xffffffffu, p0, o);
        p1 += __shfl_xor_sync(0xffffffffu, p1, o);
        p2 += __shfl_xor_sync(0xffffffffu, p2, o);
        p3 += __shfl_xor_sync(0xffffffffu, p3, o);
    }
    if (lane == 0) {
        float bc = b_cls[0];
        out[b0 + 0] = sigm(p0 + bc);
        out[b0 + 1] = sigm(p1 + bc);
        out[b0 + 2] = sigm(p2 + bc);
        out[b0 + 3] = sigm(p3 + bc);
    }
}

extern "C" void kernel_launch(void* const* d_in, const int* in_sizes, int n_in,
                              void* d_out, int out_size) {
    (void)in_sizes; (void)n_in; (void)out_size;
    const float* x     = (const float*)d_in[0];
    const float* w_ih0 = (const float*)d_in[1];
    const float* w_hh0 = (const float*)d_in[2];
    const float* b_ih0 = (const float*)d_in[3];
    const float* b_hh0 = (const float*)d_in[4];
    const float* w_ih1 = (const float*)d_in[5];
    const float* w_hh1 = (const float*)d_in[6];
    const float* b_ih1 = (const float*)d_in[7];
    const float* b_hh1 = (const float*)d_in[8];
    const float* w_cls = (const float*)d_in[9];
    const float* b_cls = (const float*)d_in[10];

    gx_gemm_kernel<<<P1_BLOCKS, P1_THREADS>>>(x, w_ih0);
    gru_recurrent_kernel<<<NBLK2, NTHR2>>>(
        w_hh0, b_ih0, b_hh0, w_ih1, w_hh1, b_ih1, b_hh1,
        w_cls, b_cls, (float*)d_out);
}